// round 15
// baseline (speedup 1.0000x reference)
#include <cuda_runtime.h>
#include <cuda_fp16.h>
#include <cstdint>

#define B_ 16
#define C_ 128
#define T_ 16384
#define H_ 4
#define D_ 32
#define CT (C_ * T_)

__device__ __half g_eq[B_ * CT];
__device__ __half g_ek[B_ * CT];
__device__ __half g_v [B_ * CT];
__device__ __half g_op[B_ * CT];
__device__ float  g_Sq[B_ * C_];
__device__ float  g_Sk[B_ * C_];
__device__ float  g_ctx[B_ * H_ * D_ * D_];
__device__ float  g_M[B_ * C_ * C_];
__device__ float  g_stats[B_ * 2];

#define MSCALE   1048576.0f        // 2^20: lift M out of fp16 subnormal range
#define IMSCALE  (1.0f / 1048576.0f)

__device__ __forceinline__ void mma_f16(float* d, const uint32_t* a, const uint32_t* b2) {
    asm volatile("mma.sync.aligned.m16n8k16.row.col.f32.f16.f16.f32 "
        "{%0,%1,%2,%3}, {%4,%5,%6,%7}, {%8,%9}, {%0,%1,%2,%3};"
        : "+f"(d[0]), "+f"(d[1]), "+f"(d[2]), "+f"(d[3])
        : "r"(a[0]), "r"(a[1]), "r"(a[2]), "r"(a[3]), "r"(b2[0]), "r"(b2[1]));
}

// ---------------- K0: zero ---------------------------------------------------
__global__ void k_zero() {
    int i = blockIdx.x * 256 + threadIdx.x;
    if (i < B_ * C_)           { g_Sq[i] = 0.f; g_Sk[i] = 0.f; }
    if (i < B_ * H_ * D_ * D_) g_ctx[i] = 0.f;
    if (i < B_ * 2)            g_stats[i] = 0.f;
}

// ---------------- K1: fused QKV GEMM, pipelined W staging --------------------
// SMEM: Bs2 (c-pair x tile) 34816B | As double-buffer 20480B | rsum 512B
#define QKV_SMEM (34816 + 20480 + 512)

__global__ __launch_bounds__(256, 2) void k_qkv(const float* __restrict__ x,
                                                const float* __restrict__ wqkv) {
    extern __shared__ char dsm[];
    __half2 (*Bs2)[136]     = (__half2(*)[136])dsm;
    __half  (*As)[128][40]  = (__half(*)[128][40])(dsm + 34816);
    float*  rsum            = (float*)(dsm + 34816 + 20480);
    const int b = blockIdx.y, t0 = blockIdx.x * 128;
    const int tid = threadIdx.x, lane = tid & 31, wid = tid >> 5;
    const int wm = (wid >> 1) * 32, wn = (wid & 1) * 64;
    const int g = lane >> 2, c2 = (lane & 3) * 2;
    const int q = lane & 3;
    const int wrow = tid >> 3, wc4 = (tid & 7) * 4;   // W staging coords (it=0)

    const float* xb = x + (size_t)b * CT;
#pragma unroll
    for (int it = 0; it < 8; it++) {                  // stage + transpose-pack x
        int idx = tid + it * 256;
        int cp = idx >> 5, t4 = (idx & 31) * 4;
        float4 v0 = *(const float4*)(xb + (size_t)(2 * cp)     * T_ + t0 + t4);
        float4 v1 = *(const float4*)(xb + (size_t)(2 * cp + 1) * T_ + t0 + t4);
        __half2 w0 = __floats2half2_rn(v0.x, v1.x);
        __half2 w1 = __floats2half2_rn(v0.y, v1.y);
        __half2 w2 = __floats2half2_rn(v0.z, v1.z);
        __half2 w3 = __floats2half2_rn(v0.w, v1.w);
        uint4 u;
        u.x = *(uint32_t*)&w0; u.y = *(uint32_t*)&w1;
        u.z = *(uint32_t*)&w2; u.w = *(uint32_t*)&w3;
        *(uint4*)&Bs2[cp][t4] = u;
    }

    for (int ot = 0; ot < 3; ot++) {
        float acc[2][8][4];
#pragma unroll
        for (int mi = 0; mi < 2; mi++)
#pragma unroll
            for (int ni = 0; ni < 8; ni++)
#pragma unroll
                for (int r = 0; r < 4; r++) acc[mi][ni][r] = 0.f;

        // prefetch W chunk 0 (converted to half at load)
        uint32_t wpre[8];
#pragma unroll
        for (int it = 0; it < 4; it++) {
            int idx = tid + it * 256, row = idx >> 3, c4 = (idx & 7) * 4;
            float4 v = *(const float4*)(wqkv + (size_t)(ot * 128 + row) * 128 + c4);
            __half2 h0 = __floats2half2_rn(v.x, v.y);
            __half2 h1 = __floats2half2_rn(v.z, v.w);
            wpre[2 * it]     = *(uint32_t*)&h0;
            wpre[2 * it + 1] = *(uint32_t*)&h1;
        }

        for (int kc = 0; kc < 4; kc++) {
            const int buf = kc & 1;
#pragma unroll
            for (int it = 0; it < 4; it++) {          // STS prefetched W chunk
                int idx = tid + it * 256, row = idx >> 3, c4 = (idx & 7) * 4;
                uint2 u; u.x = wpre[2 * it]; u.y = wpre[2 * it + 1];
                *(uint2*)&As[buf][row][c4] = u;
            }
            __syncthreads();
            if (kc < 3) {                              // overlap next-chunk LDG
#pragma unroll
                for (int it = 0; it < 4; it++) {
                    int idx = tid + it * 256, row = idx >> 3, c4 = (idx & 7) * 4;
                    float4 v = *(const float4*)(wqkv
                        + (size_t)(ot * 128 + row) * 128 + (kc + 1) * 32 + c4);
                    __half2 h0 = __floats2half2_rn(v.x, v.y);
                    __half2 h1 = __floats2half2_rn(v.z, v.w);
                    wpre[2 * it]     = *(uint32_t*)&h0;
                    wpre[2 * it + 1] = *(uint32_t*)&h1;
                }
            }
#pragma unroll
            for (int s = 0; s < 2; s++) {
                const int ks = s * 16;
                const int rb = kc * 16 + s * 8 + q;
                uint32_t af[2][4], bf[8][2];
#pragma unroll
                for (int mi = 0; mi < 2; mi++) {
                    int r = wm + mi * 16 + g;
                    af[mi][0] = *(const uint32_t*)&As[buf][r    ][ks +     c2];
                    af[mi][1] = *(const uint32_t*)&As[buf][r + 8][ks +     c2];
                    af[mi][2] = *(const uint32_t*)&As[buf][r    ][ks + 8 + c2];
                    af[mi][3] = *(const uint32_t*)&As[buf][r + 8][ks + 8 + c2];
                }
#pragma unroll
                for (int ni = 0; ni < 8; ni++) {
                    int n = wn + ni * 8 + g;
                    bf[ni][0] = *(const uint32_t*)&Bs2[rb    ][n];
                    bf[ni][1] = *(const uint32_t*)&Bs2[rb + 4][n];
                }
#pragma unroll
                for (int mi = 0; mi < 2; mi++)
#pragma unroll
                    for (int ni = 0; ni < 8; ni++)
                        mma_f16(acc[mi][ni], af[mi], bf[ni]);
            }
        }

        if (ot == 2) {
            __half* dst = g_v + (size_t)b * CT;
#pragma unroll
            for (int mi = 0; mi < 2; mi++)
#pragma unroll
                for (int half = 0; half < 2; half++) {
                    int r = wm + mi * 16 + (lane >> 2) + half * 8;
#pragma unroll
                    for (int ni = 0; ni < 8; ni++)
                        *(__half2*)(dst + (size_t)r * T_ + t0 + wn + ni * 8
                                    + 2 * (lane & 3)) =
                            __floats2half2_rn(acc[mi][ni][half * 2],
                                              acc[mi][ni][half * 2 + 1]);
                }
        } else {
            __syncthreads();
            if (tid < 128) rsum[tid] = 0.f;
            __syncthreads();
            __half* dst = (ot == 0 ? g_eq : g_ek) + (size_t)b * CT;
#pragma unroll
            for (int mi = 0; mi < 2; mi++)
#pragma unroll
                for (int half = 0; half < 2; half++) {
                    int r = wm + mi * 16 + (lane >> 2) + half * 8;
                    float s = 0.f;
#pragma unroll
                    for (int ni = 0; ni < 8; ni++) {
                        float e0 = __expf(acc[mi][ni][half * 2]);
                        float e1 = __expf(acc[mi][ni][half * 2 + 1]);
                        s += e0 + e1;
                        *(__half2*)(dst + (size_t)r * T_ + t0 + wn + ni * 8
                                    + 2 * (lane & 3)) = __floats2half2_rn(e0, e1);
                    }
                    s += __shfl_xor_sync(0xffffffffu, s, 1);
                    s += __shfl_xor_sync(0xffffffffu, s, 2);
                    if ((lane & 3) == 0) atomicAdd(&rsum[r], s);
                }
            __syncthreads();
            float* S = (ot == 0 ? g_Sq : g_Sk) + b * C_;
            if (tid < 128) atomicAdd(&S[tid], rsum[tid]);
        }
    }
    (void)wrow; (void)wc4;
}

// ---------------- K2: ctx via fp16 tensor cores (R9-proven) ------------------
__global__ __launch_bounds__(256) void k_ctx() {
    const int b = blockIdx.z, h = blockIdx.y, sp = blockIdx.x;
    const __half* K = g_ek + (size_t)(b * C_ + h * D_) * T_;
    const __half* V = g_v  + (size_t)(b * C_ + h * D_) * T_;
    __shared__ __half ekh[32][136];
    __shared__ __half vh [32][136];
    __shared__ float cacc[D_ * D_];
    const int tid = threadIdx.x, lane = tid & 31, wid = tid >> 5;
    const int g = lane >> 2, c2 = (lane & 3) * 2;
    const int kb = wid * 16;

    for (int i = tid; i < D_ * D_; i += 256) cacc[i] = 0.f;

    float acc[2][4][4];
#pragma unroll
    for (int mi = 0; mi < 2; mi++)
#pragma unroll
        for (int ni = 0; ni < 4; ni++)
#pragma unroll
            for (int r = 0; r < 4; r++) acc[mi][ni][r] = 0.f;

    for (int n0 = sp * 512; n0 < sp * 512 + 512; n0 += 128) {
        for (int i = tid; i < 512; i += 256) {
            int row = i >> 4, c8 = (i & 15) * 8;
            *(uint4*)&ekh[row][c8] = *(const uint4*)(K + (size_t)row * T_ + n0 + c8);
            *(uint4*)&vh [row][c8] = *(const uint4*)(V + (size_t)row * T_ + n0 + c8);
        }
        __syncthreads();
        uint32_t af[2][4], bf[4][2];
#pragma unroll
        for (int mi = 0; mi < 2; mi++) {
            int r = mi * 16 + g;
            af[mi][0] = *(const uint32_t*)&ekh[r    ][kb +     c2];
            af[mi][1] = *(const uint32_t*)&ekh[r + 8][kb +     c2];
            af[mi][2] = *(const uint32_t*)&ekh[r    ][kb + 8 + c2];
            af[mi][3] = *(const uint32_t*)&ekh[r + 8][kb + 8 + c2];
        }
#pragma unroll
        for (int ni = 0; ni < 4; ni++) {
            int n = ni * 8 + g;
            bf[ni][0] = *(const uint32_t*)&vh[n][kb +     c2];
            bf[ni][1] = *(const uint32_t*)&vh[n][kb + 8 + c2];
        }
#pragma unroll
        for (int mi = 0; mi < 2; mi++)
#pragma unroll
            for (int ni = 0; ni < 4; ni++)
                mma_f16(acc[mi][ni], af[mi], bf[ni]);
        __syncthreads();
    }
#pragma unroll
    for (int mi = 0; mi < 2; mi++)
#pragma unroll
        for (int ni = 0; ni < 4; ni++)
#pragma unroll
            for (int r = 0; r < 4; r++) {
                int d = mi * 16 + g + (r >> 1) * 8;
                int e = ni * 8 + c2 + (r & 1);
                atomicAdd(&cacc[d * D_ + e], acc[mi][ni][r]);
            }
    __syncthreads();
    float* Cp = g_ctx + (size_t)(b * H_ + h) * (D_ * D_);
    for (int i = tid; i < D_ * D_; i += 256) atomicAdd(&Cp[i], cacc[i]);
}

// ---------------- K3: fused M = W_out x (scaled ctx) -------------------------
__global__ __launch_bounds__(256) void k_M(const float* __restrict__ w_out) {
    const int oseg = blockIdx.x, b = blockIdx.y;
    __shared__ float cf[H_ * D_ * 33];
    const int tid = threadIdx.x;
    const float scale = 0.17677669529663687f;  // 32^-0.5
    for (int i = tid; i < H_ * D_ * D_; i += 256) {
        int h = i >> 10, d = (i >> 5) & 31, e = i & 31;
        float sk = g_Sk[b * C_ + h * D_ + d], sq = g_Sq[b * C_ + h * D_ + d];
        cf[(h * D_ + d) * 33 + e] =
            scale * g_ctx[b * (H_ * D_ * D_) + i] / (sk * sq);
    }
    __syncthreads();
    for (int i = tid; i < 4 * C_; i += 256) {
        int o = oseg * 4 + (i >> 7), hd = i & 127;
        int h = hd >> 5, d = hd & 31;
        const float* wr = w_out + o * C_ + h * D_;
        const float* cr = cf + (h * D_ + d) * 33;
        float s = 0.f;
#pragma unroll
        for (int e = 0; e < 32; e++) s = fmaf(wr[e], cr[e], s);
        g_M[b * (C_ * C_) + o * C_ + hd] = s;
    }
}

// ---------------- K4: out = M @ eq, pipelined staging; bias; GN moments ------
__global__ __launch_bounds__(256, 2) void k_out(const float* __restrict__ b_out) {
    __shared__ __align__(16) __half  As[2][128][40];   // M chunks (double buf)
    __shared__ __align__(16) __half2 Bs2[2][16][136];  // eq chunks (double buf)
    const int b = blockIdx.y, t0 = blockIdx.x * 128;
    const int tid = threadIdx.x, lane = tid & 31, wid = tid >> 5;
    const int wm = (wid >> 1) * 32, wn = (wid & 1) * 64;
    const int g = lane >> 2, c2 = (lane & 3) * 2;
    const int q = lane & 3;

    const float*  Ag = g_M + b * 128 * 128;
    const __half* Bg = g_eq + (size_t)b * CT;

    float acc[2][8][4];
#pragma unroll
    for (int mi = 0; mi < 2; mi++)
#pragma unroll
        for (int ni = 0; ni < 8; ni++)
#pragma unroll
            for (int r = 0; r < 4; r++) acc[mi][ni][r] = 0.f;

    // prefetch chunk 0: M (scaled->half) + eq (raw)
    uint32_t mpre[8];
#pragma unroll
    for (int it = 0; it < 4; it++) {
        int idx = tid + it * 256, row = idx >> 3, c4 = (idx & 7) * 4;
        float4 v = *(const float4*)(Ag + row * 128 + c4);
        __half2 h0 = __floats2half2_rn(v.x * MSCALE, v.y * MSCALE);
        __half2 h1 = __floats2half2_rn(v.z * MSCALE, v.w * MSCALE);
        mpre[2 * it]     = *(uint32_t*)&h0;
        mpre[2 * it + 1] = *(uint32_t*)&h1;
    }
    const int pcp = tid >> 4, pt8 = (tid & 15) * 8;
    uint4 bp0 = *(const uint4*)(Bg + (size_t)(2 * pcp)     * T_ + t0 + pt8);
    uint4 bp1 = *(const uint4*)(Bg + (size_t)(2 * pcp + 1) * T_ + t0 + pt8);

    for (int kc = 0; kc < 4; kc++) {
        const int buf = kc & 1;
#pragma unroll
        for (int it = 0; it < 4; it++) {            // STS M chunk
            int idx = tid + it * 256, row = idx >> 3, c4 = (idx & 7) * 4;
            uint2 u; u.x = mpre[2 * it]; u.y = mpre[2 * it + 1];
            *(uint2*)&As[buf][row][c4] = u;
        }
        {                                           // STS eq chunk (interleave)
            const __half* h0 = (const __half*)&bp0;
            const __half* h1 = (const __half*)&bp1;
            uint4 u0, u1; __half2 w;
            w = __halves2half2(h0[0], h1[0]); u0.x = *(uint32_t*)&w;
            w = __halves2half2(h0[1], h1[1]); u0.y = *(uint32_t*)&w;
            w = __halves2half2(h0[2], h1[2]); u0.z = *(uint32_t*)&w;
            w = __halves2half2(h0[3], h1[3]); u0.w = *(uint32_t*)&w;
            w = __halves2half2(h0[4], h1[4]); u1.x = *(uint32_t*)&w;
            w = __halves2half2(h0[5], h1[5]); u1.y = *(uint32_t*)&w;
            w = __halves2half2(h0[6], h1[6]); u1.z = *(uint32_t*)&w;
            w = __halves2half2(h0[7], h1[7]); u1.w = *(uint32_t*)&w;
            *(uint4*)&Bs2[buf][pcp][pt8]     = u0;
            *(uint4*)&Bs2[buf][pcp][pt8 + 4] = u1;
        }
        __syncthreads();
        if (kc < 3) {                               // overlap next-chunk LDG
#pragma unroll
            for (int it = 0; it < 4; it++) {
                int idx = tid + it * 256, row = idx >> 3, c4 = (idx & 7) * 4;
                float4 v = *(const float4*)(Ag + row * 128 + (kc + 1) * 32 + c4);
                __half2 h0 = __floats2half2_rn(v.x * MSCALE, v.y * MSCALE);
                __half2 h1 = __floats2half2_rn(v.z * MSCALE, v.w * MSCALE);
                mpre[2 * it]     = *(uint32_t*)&h0;
                mpre[2 * it + 1] = *(uint32_t*)&h1;
            }
            bp0 = *(const uint4*)(Bg + (size_t)((kc + 1) * 32 + 2 * pcp)     * T_
                                  + t0 + pt8);
            bp1 = *(const uint4*)(Bg + (size_t)((kc + 1) * 32 + 2 * pcp + 1) * T_
                                  + t0 + pt8);
        }
#pragma unroll
        for (int s = 0; s < 2; s++) {
            const int ks = s * 16;
            const int rb = s * 8 + q;
            uint32_t af[2][4], bf[8][2];
#pragma unroll
            for (int mi = 0; mi < 2; mi++) {
                int r = wm + mi * 16 + g;
                af[mi][0] = *(const uint32_t*)&As[buf][r    ][ks +     c2];
                af[mi][1] = *(const uint32_t*)&As[buf][r + 8][ks +     c2];
                af[mi][2] = *(const uint32_t*)&As[buf][r    ][ks + 8 + c2];
                af[mi][3] = *(const uint32_t*)&As[buf][r + 8][ks + 8 + c2];
            }
#pragma unroll
            for (int ni = 0; ni < 8; ni++) {
                int n = wn + ni * 8 + g;
                bf[ni][0] = *(const uint32_t*)&Bs2[buf][rb    ][n];
                bf[ni][1] = *(const uint32_t*)&Bs2[buf][rb + 4][n];
            }
#pragma unroll
            for (int mi = 0; mi < 2; mi++)
#pragma unroll
                for (int ni = 0; ni < 8; ni++)
                    mma_f16(acc[mi][ni], af[mi], bf[ni]);
        }
    }

    __half* dst = g_op + (size_t)b * CT;
    float s1 = 0.f, s2 = 0.f;
#pragma unroll
    for (int mi = 0; mi < 2; mi++)
#pragma unroll
        for (int half = 0; half < 2; half++) {
            int r = wm + mi * 16 + (lane >> 2) + half * 8;
            float bo = __ldg(&b_out[r]);
#pragma unroll
            for (int ni = 0; ni < 8; ni++) {
                float v0 = acc[mi][ni][half * 2]     * IMSCALE + bo;
                float v1 = acc[mi][ni][half * 2 + 1] * IMSCALE + bo;
                s1 += v0 + v1;
                s2 = fmaf(v0, v0, s2); s2 = fmaf(v1, v1, s2);
                *(__half2*)(dst + (size_t)r * T_ + t0 + wn + ni * 8
                            + 2 * (lane & 3)) = __floats2half2_rn(v0, v1);
            }
        }
#pragma unroll
    for (int o = 16; o > 0; o >>= 1) {
        s1 += __shfl_down_sync(0xffffffffu, s1, o);
        s2 += __shfl_down_sync(0xffffffffu, s2, o);
    }
    if (lane == 0) {
        atomicAdd(&g_stats[b * 2 + 0], s1);
        atomicAdd(&g_stats[b * 2 + 1], s2);
    }
}

// ---------------- K5: GroupNorm finalize (reads fp16 op) ---------------------
__global__ void k_norm(const float* __restrict__ gnw,
                       const float* __restrict__ gnb,
                       float* __restrict__ out) {
    int i4 = blockIdx.x * 256 + threadIdx.x;
    int e  = i4 * 4;
    int b  = e >> 21;
    int c  = (e >> 14) & 127;
    const float inv = 1.0f / (float)CT;
    float m    = g_stats[b * 2 + 0] * inv;
    float var  = g_stats[b * 2 + 1] * inv - m * m;
    float rstd = rsqrtf(var + 1e-5f);
    float w    = gnw[c] * rstd;
    float bias = gnb[c] - m * w;
    const __half2* src = (const __half2*)(g_op + e);
    float2 p0 = __half22float2(src[0]);
    float2 p1 = __half22float2(src[1]);
    float4 v = make_float4(p0.x * w + bias, p0.y * w + bias,
                           p1.x * w + bias, p1.y * w + bias);
    *(float4*)(out + e) = v;
}

// ---------------- launch ------------------------------------------------------
extern "C" void kernel_launch(void* const* d_in, const int* in_sizes, int n_in,
                              void* d_out, int out_size)
{
    const float* x    = (const float*)d_in[0];
    const float* wqkv = (const float*)d_in[1];
    const float* wout = (const float*)d_in[2];
    const float* bout = (const float*)d_in[3];
    const float* gnw  = (const float*)d_in[4];
    const float* gnb  = (const float*)d_in[5];
    float* out = (float*)d_out;

    cudaFuncSetAttribute(k_qkv, cudaFuncAttributeMaxDynamicSharedMemorySize,
                         QKV_SMEM);

    k_zero<<<256, 256>>>();
    k_qkv<<<dim3(T_ / 128, B_), 256, QKV_SMEM>>>(x, wqkv);
    k_ctx<<<dim3(32, H_, B_), 256>>>();
    k_M<<<dim3(32, B_), 256>>>(wout);
    k_out<<<dim3(T_ / 128, B_), 256>>>(bout);
    k_norm<<<32768, 256>>>(gnw, gnb, out);
}

// round 16
// speedup vs baseline: 1.0505x; 1.0505x over previous
#include <cuda_runtime.h>
#include <cuda_fp16.h>
#include <cstdint>

#define B_ 16
#define C_ 128
#define T_ 16384
#define H_ 4
#define D_ 32
#define CT (C_ * T_)

__device__ __half g_eq[B_ * CT];
__device__ __half g_ek[B_ * CT];
__device__ __half g_v [B_ * CT];
__device__ __half g_op[B_ * CT];
__device__ float  g_Sq[B_ * C_];
__device__ float  g_Sk[B_ * C_];
__device__ float  g_ctx[B_ * H_ * D_ * D_];
__device__ float  g_M[B_ * C_ * C_];
__device__ float  g_stats[B_ * 2];

#define MSCALE   1048576.0f        // 2^20: lift M out of fp16 subnormal range
#define IMSCALE  (1.0f / 1048576.0f)

__device__ __forceinline__ void mma_f16(float* d, const uint32_t* a, const uint32_t* b2) {
    asm volatile("mma.sync.aligned.m16n8k16.row.col.f32.f16.f16.f32 "
        "{%0,%1,%2,%3}, {%4,%5,%6,%7}, {%8,%9}, {%0,%1,%2,%3};"
        : "+f"(d[0]), "+f"(d[1]), "+f"(d[2]), "+f"(d[3])
        : "r"(a[0]), "r"(a[1]), "r"(a[2]), "r"(a[3]), "r"(b2[0]), "r"(b2[1]));
}

// ---------------- K0: zero ---------------------------------------------------
__global__ void k_zero() {
    int i = blockIdx.x * 256 + threadIdx.x;
    if (i < B_ * C_)           { g_Sq[i] = 0.f; g_Sk[i] = 0.f; }
    if (i < B_ * H_ * D_ * D_) g_ctx[i] = 0.f;
    if (i < B_ * 2)            g_stats[i] = 0.f;
}

// ---------------- K1: fused QKV GEMM, full-slab W staging --------------------
// Layout: Bs2 c-pair x tile (34816B) | As full W slab [128][136] half (34816B)
// | rsum (512B). One sync per ot; the 8 k-step mma loop is barrier-free.
#define QKV_SMEM (34816 + 34816 + 512)

__global__ __launch_bounds__(256, 2) void k_qkv(const float* __restrict__ x,
                                                const float* __restrict__ wqkv) {
    extern __shared__ char dsm[];
    __half2 (*Bs2)[136] = (__half2(*)[136])dsm;
    __half  (*As)[136]  = (__half(*)[136])(dsm + 34816);
    float*  rsum        = (float*)(dsm + 34816 + 34816);
    const int b = blockIdx.y, t0 = blockIdx.x * 128;
    const int tid = threadIdx.x, lane = tid & 31, wid = tid >> 5;
    const int wm = (wid >> 1) * 32, wn = (wid & 1) * 64;
    const int g = lane >> 2, c2 = (lane & 3) * 2;
    const int q = lane & 3;

    const float* xb = x + (size_t)b * CT;
#pragma unroll
    for (int it = 0; it < 8; it++) {                  // stage + transpose-pack x
        int idx = tid + it * 256;
        int cp = idx >> 5, t4 = (idx & 31) * 4;
        float4 v0 = *(const float4*)(xb + (size_t)(2 * cp)     * T_ + t0 + t4);
        float4 v1 = *(const float4*)(xb + (size_t)(2 * cp + 1) * T_ + t0 + t4);
        __half2 w0 = __floats2half2_rn(v0.x, v1.x);
        __half2 w1 = __floats2half2_rn(v0.y, v1.y);
        __half2 w2 = __floats2half2_rn(v0.z, v1.z);
        __half2 w3 = __floats2half2_rn(v0.w, v1.w);
        uint4 u;
        u.x = *(uint32_t*)&w0; u.y = *(uint32_t*)&w1;
        u.z = *(uint32_t*)&w2; u.w = *(uint32_t*)&w3;
        *(uint4*)&Bs2[cp][t4] = u;
    }

    for (int ot = 0; ot < 3; ot++) {
        // stage FULL W slab for this ot (L2-hot; 16 float4 per thread)
#pragma unroll
        for (int it = 0; it < 16; it++) {
            int idx = tid + it * 256, row = idx >> 5, c4 = (idx & 31) * 4;
            float4 v = *(const float4*)(wqkv + (size_t)(ot * 128 + row) * 128 + c4);
            __half2 h0 = __floats2half2_rn(v.x, v.y);
            __half2 h1 = __floats2half2_rn(v.z, v.w);
            uint2 u; u.x = *(uint32_t*)&h0; u.y = *(uint32_t*)&h1;
            *(uint2*)&As[row][c4] = u;
        }
        __syncthreads();

        float acc[2][8][4];
#pragma unroll
        for (int mi = 0; mi < 2; mi++)
#pragma unroll
            for (int ni = 0; ni < 8; ni++)
#pragma unroll
                for (int r = 0; r < 4; r++) acc[mi][ni][r] = 0.f;

#pragma unroll
        for (int kc = 0; kc < 4; kc++) {
#pragma unroll
            for (int s = 0; s < 2; s++) {
                const int kcol = kc * 32 + s * 16;
                const int rb = kc * 16 + s * 8 + q;
                uint32_t af[2][4], bf[8][2];
#pragma unroll
                for (int mi = 0; mi < 2; mi++) {
                    int r = wm + mi * 16 + g;
                    af[mi][0] = *(const uint32_t*)&As[r    ][kcol +     c2];
                    af[mi][1] = *(const uint32_t*)&As[r + 8][kcol +     c2];
                    af[mi][2] = *(const uint32_t*)&As[r    ][kcol + 8 + c2];
                    af[mi][3] = *(const uint32_t*)&As[r + 8][kcol + 8 + c2];
                }
#pragma unroll
                for (int ni = 0; ni < 8; ni++) {
                    int n = wn + ni * 8 + g;
                    bf[ni][0] = *(const uint32_t*)&Bs2[rb    ][n];
                    bf[ni][1] = *(const uint32_t*)&Bs2[rb + 4][n];
                }
#pragma unroll
                for (int mi = 0; mi < 2; mi++)
#pragma unroll
                    for (int ni = 0; ni < 8; ni++)
                        mma_f16(acc[mi][ni], af[mi], bf[ni]);
            }
        }

        if (ot == 2) {
            __half* dst = g_v + (size_t)b * CT;
#pragma unroll
            for (int mi = 0; mi < 2; mi++)
#pragma unroll
                for (int half = 0; half < 2; half++) {
                    int r = wm + mi * 16 + (lane >> 2) + half * 8;
#pragma unroll
                    for (int ni = 0; ni < 8; ni++)
                        *(__half2*)(dst + (size_t)r * T_ + t0 + wn + ni * 8
                                    + 2 * (lane & 3)) =
                            __floats2half2_rn(acc[mi][ni][half * 2],
                                              acc[mi][ni][half * 2 + 1]);
                }
        } else {
            // syncs here also protect As against restaging by the next ot
            __syncthreads();
            if (tid < 128) rsum[tid] = 0.f;
            __syncthreads();
            __half* dst = (ot == 0 ? g_eq : g_ek) + (size_t)b * CT;
#pragma unroll
            for (int mi = 0; mi < 2; mi++)
#pragma unroll
                for (int half = 0; half < 2; half++) {
                    int r = wm + mi * 16 + (lane >> 2) + half * 8;
                    float s = 0.f;
#pragma unroll
                    for (int ni = 0; ni < 8; ni++) {
                        float e0 = __expf(acc[mi][ni][half * 2]);
                        float e1 = __expf(acc[mi][ni][half * 2 + 1]);
                        s += e0 + e1;
                        *(__half2*)(dst + (size_t)r * T_ + t0 + wn + ni * 8
                                    + 2 * (lane & 3)) = __floats2half2_rn(e0, e1);
                    }
                    s += __shfl_xor_sync(0xffffffffu, s, 1);
                    s += __shfl_xor_sync(0xffffffffu, s, 2);
                    if ((lane & 3) == 0) atomicAdd(&rsum[r], s);
                }
            __syncthreads();
            float* S = (ot == 0 ? g_Sq : g_Sk) + b * C_;
            if (tid < 128) atomicAdd(&S[tid], rsum[tid]);
        }
    }
}

// ---------------- K2: ctx via fp16 tensor cores (R9-proven) ------------------
__global__ __launch_bounds__(256) void k_ctx() {
    const int b = blockIdx.z, h = blockIdx.y, sp = blockIdx.x;
    const __half* K = g_ek + (size_t)(b * C_ + h * D_) * T_;
    const __half* V = g_v  + (size_t)(b * C_ + h * D_) * T_;
    __shared__ __half ekh[32][136];
    __shared__ __half vh [32][136];
    __shared__ float cacc[D_ * D_];
    const int tid = threadIdx.x, lane = tid & 31, wid = tid >> 5;
    const int g = lane >> 2, c2 = (lane & 3) * 2;
    const int kb = wid * 16;

    for (int i = tid; i < D_ * D_; i += 256) cacc[i] = 0.f;

    float acc[2][4][4];
#pragma unroll
    for (int mi = 0; mi < 2; mi++)
#pragma unroll
        for (int ni = 0; ni < 4; ni++)
#pragma unroll
            for (int r = 0; r < 4; r++) acc[mi][ni][r] = 0.f;

    for (int n0 = sp * 512; n0 < sp * 512 + 512; n0 += 128) {
        for (int i = tid; i < 512; i += 256) {
            int row = i >> 4, c8 = (i & 15) * 8;
            *(uint4*)&ekh[row][c8] = *(const uint4*)(K + (size_t)row * T_ + n0 + c8);
            *(uint4*)&vh [row][c8] = *(const uint4*)(V + (size_t)row * T_ + n0 + c8);
        }
        __syncthreads();
        uint32_t af[2][4], bf[4][2];
#pragma unroll
        for (int mi = 0; mi < 2; mi++) {
            int r = mi * 16 + g;
            af[mi][0] = *(const uint32_t*)&ekh[r    ][kb +     c2];
            af[mi][1] = *(const uint32_t*)&ekh[r + 8][kb +     c2];
            af[mi][2] = *(const uint32_t*)&ekh[r    ][kb + 8 + c2];
            af[mi][3] = *(const uint32_t*)&ekh[r + 8][kb + 8 + c2];
        }
#pragma unroll
        for (int ni = 0; ni < 4; ni++) {
            int n = ni * 8 + g;
            bf[ni][0] = *(const uint32_t*)&vh[n][kb +     c2];
            bf[ni][1] = *(const uint32_t*)&vh[n][kb + 8 + c2];
        }
#pragma unroll
        for (int mi = 0; mi < 2; mi++)
#pragma unroll
            for (int ni = 0; ni < 4; ni++)
                mma_f16(acc[mi][ni], af[mi], bf[ni]);
        __syncthreads();
    }
#pragma unroll
    for (int mi = 0; mi < 2; mi++)
#pragma unroll
        for (int ni = 0; ni < 4; ni++)
#pragma unroll
            for (int r = 0; r < 4; r++) {
                int d = mi * 16 + g + (r >> 1) * 8;
                int e = ni * 8 + c2 + (r & 1);
                atomicAdd(&cacc[d * D_ + e], acc[mi][ni][r]);
            }
    __syncthreads();
    float* Cp = g_ctx + (size_t)(b * H_ + h) * (D_ * D_);
    for (int i = tid; i < D_ * D_; i += 256) atomicAdd(&Cp[i], cacc[i]);
}

// ---------------- K3: fused M = W_out x (scaled ctx) -------------------------
__global__ __launch_bounds__(256) void k_M(const float* __restrict__ w_out) {
    const int oseg = blockIdx.x, b = blockIdx.y;
    __shared__ float cf[H_ * D_ * 33];
    const int tid = threadIdx.x;
    const float scale = 0.17677669529663687f;  // 32^-0.5
    for (int i = tid; i < H_ * D_ * D_; i += 256) {
        int h = i >> 10, d = (i >> 5) & 31, e = i & 31;
        float sk = g_Sk[b * C_ + h * D_ + d], sq = g_Sq[b * C_ + h * D_ + d];
        cf[(h * D_ + d) * 33 + e] =
            scale * g_ctx[b * (H_ * D_ * D_) + i] / (sk * sq);
    }
    __syncthreads();
    for (int i = tid; i < 4 * C_; i += 256) {
        int o = oseg * 4 + (i >> 7), hd = i & 127;
        int h = hd >> 5, d = hd & 31;
        const float* wr = w_out + o * C_ + h * D_;
        const float* cr = cf + (h * D_ + d) * 33;
        float s = 0.f;
#pragma unroll
        for (int e = 0; e < 32; e++) s = fmaf(wr[e], cr[e], s);
        g_M[b * (C_ * C_) + o * C_ + hd] = s;
    }
}

// ---------------- K4: out = M @ eq; full-M staging + dbl-buf eq chunks -------
// Layout: As full M [128][136] half (34816B) | Bs2[2][16][136] half2 (17408B)
#define OUT_SMEM (34816 + 17408)

__global__ __launch_bounds__(256, 2) void k_out(const float* __restrict__ b_out) {
    extern __shared__ char dsm[];
    __half  (*As)[136]      = (__half(*)[136])dsm;
    __half2 (*Bs2)[16][136] = (__half2(*)[16][136])(dsm + 34816);
    const int b = blockIdx.y, t0 = blockIdx.x * 128;
    const int tid = threadIdx.x, lane = tid & 31, wid = tid >> 5;
    const int wm = (wid >> 1) * 32, wn = (wid & 1) * 64;
    const int g = lane >> 2, c2 = (lane & 3) * 2;
    const int q = lane & 3;

    const float*  Ag = g_M + b * 128 * 128;
    const __half* Bg = g_eq + (size_t)b * CT;

    // stage FULL M (scaled -> half) once
#pragma unroll
    for (int it = 0; it < 16; it++) {
        int idx = tid + it * 256, row = idx >> 5, c4 = (idx & 31) * 4;
        float4 v = *(const float4*)(Ag + row * 128 + c4);
        __half2 h0 = __floats2half2_rn(v.x * MSCALE, v.y * MSCALE);
        __half2 h1 = __floats2half2_rn(v.z * MSCALE, v.w * MSCALE);
        uint2 u; u.x = *(uint32_t*)&h0; u.y = *(uint32_t*)&h1;
        *(uint2*)&As[row][c4] = u;
    }

    float acc[2][8][4];
#pragma unroll
    for (int mi = 0; mi < 2; mi++)
#pragma unroll
        for (int ni = 0; ni < 8; ni++)
#pragma unroll
            for (int r = 0; r < 4; r++) acc[mi][ni][r] = 0.f;

    const int pcp = tid >> 4, pt8 = (tid & 15) * 8;
    uint4 bp0 = *(const uint4*)(Bg + (size_t)(2 * pcp)     * T_ + t0 + pt8);
    uint4 bp1 = *(const uint4*)(Bg + (size_t)(2 * pcp + 1) * T_ + t0 + pt8);

    for (int kc = 0; kc < 4; kc++) {
        const int buf = kc & 1;
        {                                           // STS eq chunk (interleave)
            const __half* h0 = (const __half*)&bp0;
            const __half* h1 = (const __half*)&bp1;
            uint4 u0, u1; __half2 w;
            w = __halves2half2(h0[0], h1[0]); u0.x = *(uint32_t*)&w;
            w = __halves2half2(h0[1], h1[1]); u0.y = *(uint32_t*)&w;
            w = __halves2half2(h0[2], h1[2]); u0.z = *(uint32_t*)&w;
            w = __halves2half2(h0[3], h1[3]); u0.w = *(uint32_t*)&w;
            w = __halves2half2(h0[4], h1[4]); u1.x = *(uint32_t*)&w;
            w = __halves2half2(h0[5], h1[5]); u1.y = *(uint32_t*)&w;
            w = __halves2half2(h0[6], h1[6]); u1.z = *(uint32_t*)&w;
            w = __halves2half2(h0[7], h1[7]); u1.w = *(uint32_t*)&w;
            *(uint4*)&Bs2[buf][pcp][pt8]     = u0;
            *(uint4*)&Bs2[buf][pcp][pt8 + 4] = u1;
        }
        __syncthreads();        // also covers the initial As staging at kc=0
        if (kc < 3) {           // overlap next-chunk LDG with mma below
            bp0 = *(const uint4*)(Bg + (size_t)((kc + 1) * 32 + 2 * pcp)     * T_
                                  + t0 + pt8);
            bp1 = *(const uint4*)(Bg + (size_t)((kc + 1) * 32 + 2 * pcp + 1) * T_
                                  + t0 + pt8);
        }
#pragma unroll
        for (int s = 0; s < 2; s++) {
            const int kcol = kc * 32 + s * 16;
            const int rb = s * 8 + q;
            uint32_t af[2][4], bf[8][2];
#pragma unroll
            for (int mi = 0; mi < 2; mi++) {
                int r = wm + mi * 16 + g;
                af[mi][0] = *(const uint32_t*)&As[r    ][kcol +     c2];
                af[mi][1] = *(const uint32_t*)&As[r + 8][kcol +     c2];
                af[mi][2] = *(const uint32_t*)&As[r    ][kcol + 8 + c2];
                af[mi][3] = *(const uint32_t*)&As[r + 8][kcol + 8 + c2];
            }
#pragma unroll
            for (int ni = 0; ni < 8; ni++) {
                int n = wn + ni * 8 + g;
                bf[ni][0] = *(const uint32_t*)&Bs2[buf][rb    ][n];
                bf[ni][1] = *(const uint32_t*)&Bs2[buf][rb + 4][n];
            }
#pragma unroll
            for (int mi = 0; mi < 2; mi++)
#pragma unroll
                for (int ni = 0; ni < 8; ni++)
                    mma_f16(acc[mi][ni], af[mi], bf[ni]);
        }
    }

    __half* dst = g_op + (size_t)b * CT;
    float s1 = 0.f, s2 = 0.f;
#pragma unroll
    for (int mi = 0; mi < 2; mi++)
#pragma unroll
        for (int half = 0; half < 2; half++) {
            int r = wm + mi * 16 + (lane >> 2) + half * 8;
            float bo = __ldg(&b_out[r]);
#pragma unroll
            for (int ni = 0; ni < 8; ni++) {
                float v0 = acc[mi][ni][half * 2]     * IMSCALE + bo;
                float v1 = acc[mi][ni][half * 2 + 1] * IMSCALE + bo;
                s1 += v0 + v1;
                s2 = fmaf(v0, v0, s2); s2 = fmaf(v1, v1, s2);
                *(__half2*)(dst + (size_t)r * T_ + t0 + wn + ni * 8
                            + 2 * (lane & 3)) = __floats2half2_rn(v0, v1);
            }
        }
#pragma unroll
    for (int o = 16; o > 0; o >>= 1) {
        s1 += __shfl_down_sync(0xffffffffu, s1, o);
        s2 += __shfl_down_sync(0xffffffffu, s2, o);
    }
    if (lane == 0) {
        atomicAdd(&g_stats[b * 2 + 0], s1);
        atomicAdd(&g_stats[b * 2 + 1], s2);
    }
}

// ---------------- K5: GroupNorm finalize (reads fp16 op) ---------------------
__global__ void k_norm(const float* __restrict__ gnw,
                       const float* __restrict__ gnb,
                       float* __restrict__ out) {
    int i4 = blockIdx.x * 256 + threadIdx.x;
    int e  = i4 * 4;
    int b  = e >> 21;
    int c  = (e >> 14) & 127;
    const float inv = 1.0f / (float)CT;
    float m    = g_stats[b * 2 + 0] * inv;
    float var  = g_stats[b * 2 + 1] * inv - m * m;
    float rstd = rsqrtf(var + 1e-5f);
    float w    = gnw[c] * rstd;
    float bias = gnb[c] - m * w;
    const __half2* src = (const __half2*)(g_op + e);
    float2 p0 = __half22float2(src[0]);
    float2 p1 = __half22float2(src[1]);
    float4 v = make_float4(p0.x * w + bias, p0.y * w + bias,
                           p1.x * w + bias, p1.y * w + bias);
    *(float4*)(out + e) = v;
}

// ---------------- launch ------------------------------------------------------
extern "C" void kernel_launch(void* const* d_in, const int* in_sizes, int n_in,
                              void* d_out, int out_size)
{
    const float* x    = (const float*)d_in[0];
    const float* wqkv = (const float*)d_in[1];
    const float* wout = (const float*)d_in[2];
    const float* bout = (const float*)d_in[3];
    const float* gnw  = (const float*)d_in[4];
    const float* gnb  = (const float*)d_in[5];
    float* out = (float*)d_out;

    cudaFuncSetAttribute(k_qkv, cudaFuncAttributeMaxDynamicSharedMemorySize,
                         QKV_SMEM);
    cudaFuncSetAttribute(k_out, cudaFuncAttributeMaxDynamicSharedMemorySize,
                         OUT_SMEM);

    k_zero<<<256, 256>>>();
    k_qkv<<<dim3(T_ / 128, B_), 256, QKV_SMEM>>>(x, wqkv);
    k_ctx<<<dim3(32, H_, B_), 256>>>();
    k_M<<<dim3(32, B_), 256>>>(wout);
    k_out<<<dim3(T_ / 128, B_), 256, OUT_SMEM>>>(bout);
    k_norm<<<32768, 256>>>(gnw, gnb, out);
}